// round 3
// baseline (speedup 1.0000x reference)
#include <cuda_runtime.h>
#include <cuda_bf16.h>
#include <cstdint>

#define N_NODES 100000
#define N_EDGES 1600000
#define F_IN    128
#define F_HID   64
#define F_OUT   40

#define SCAN_T  1024
#define SCAN_NB ((N_NODES + SCAN_T - 1) / SCAN_T)   // 98

// ---------------- scratch (static device globals; no allocation) ----------------
__device__ int   g_degs_i[N_NODES];
__device__ int   g_degd_i[N_NODES];
__device__ float g_ns[N_NODES];
__device__ float g_nd[N_NODES];
__device__ int   g_incl[N_NODES];
__device__ int   g_rowoff[N_NODES + 1];
__device__ int   g_cursor[N_NODES];
__device__ int   g_partial[SCAN_NB];
__device__ int   g_poff[SCAN_NB];
__device__ int   g_csrc[N_EDGES];
__device__ float g_bufA[(size_t)N_NODES * F_HID];
__device__ float g_bufB[(size_t)N_NODES * F_HID];
__device__ float g_bufC[(size_t)N_NODES * F_OUT];

// ---------------- degree histograms ----------------
__global__ void k_zero_deg() {
    int i = blockIdx.x * blockDim.x + threadIdx.x;
    if (i < N_NODES) { g_degs_i[i] = 0; g_degd_i[i] = 0; }
}

__global__ void k_deg(const int* __restrict__ src, const int* __restrict__ dst) {
    int e = blockIdx.x * blockDim.x + threadIdx.x;
    if (e < N_EDGES) {
        atomicAdd(&g_degs_i[src[e]], 1);
        atomicAdd(&g_degd_i[dst[e]], 1);
    }
}

// ---------------- CSR build ----------------
__global__ __launch_bounds__(SCAN_T) void k_scan_block() {
    __shared__ int ws[32];
    int g = blockIdx.x * SCAN_T + threadIdx.x;
    int lane = threadIdx.x & 31, wid = threadIdx.x >> 5;
    int x = (g < N_NODES) ? g_degd_i[g] : 0;
#pragma unroll
    for (int o = 1; o < 32; o <<= 1) {
        int y = __shfl_up_sync(0xFFFFFFFFu, x, o);
        if (lane >= o) x += y;
    }
    if (lane == 31) ws[wid] = x;
    __syncthreads();
    if (wid == 0) {
        int y = ws[lane];
#pragma unroll
        for (int o = 1; o < 32; o <<= 1) {
            int z = __shfl_up_sync(0xFFFFFFFFu, y, o);
            if (lane >= o) y += z;
        }
        ws[lane] = y;
    }
    __syncthreads();
    int incl = x + (wid > 0 ? ws[wid - 1] : 0);
    if (g < N_NODES) g_incl[g] = incl;
    if (threadIdx.x == SCAN_T - 1) g_partial[blockIdx.x] = incl;
}

// parallel scan of the 98 block partials (1 block, 128 threads)
__global__ __launch_bounds__(128) void k_scan_partials() {
    __shared__ int ws[4];
    const int t = threadIdx.x;
    const int lane = t & 31, w = t >> 5;
    const int v = (t < SCAN_NB) ? g_partial[t] : 0;
    int x = v;
#pragma unroll
    for (int o = 1; o < 32; o <<= 1) {
        int y = __shfl_up_sync(0xFFFFFFFFu, x, o);
        if (lane >= o) x += y;
    }
    if (lane == 31) ws[w] = x;
    __syncthreads();
    int off = 0;
#pragma unroll
    for (int i = 0; i < 4; i++) if (i < w) off += ws[i];
    if (t < SCAN_NB) g_poff[t] = x + off - v;   // exclusive prefix
}

// finalize rowoff/cursor + compute both norms (folded k_norm)
__global__ __launch_bounds__(SCAN_T) void k_finalize() {
    int g = blockIdx.x * SCAN_T + threadIdx.x;
    if (g < N_NODES) {
        int dd  = g_degd_i[g];
        int incl = g_incl[g] + g_poff[blockIdx.x];
        g_rowoff[g + 1] = incl;
        g_cursor[g] = incl - dd;
        if (g == 0) g_rowoff[0] = 0;
        g_ns[g] = rsqrtf(fmaxf((float)g_degs_i[g], 1.0f));
        g_nd[g] = rsqrtf(fmaxf((float)dd, 1.0f));
    }
}

__global__ void k_fill(const int* __restrict__ src, const int* __restrict__ dst) {
    int e = blockIdx.x * blockDim.x + threadIdx.x;
    if (e < N_EDGES) {
        int d = dst[e];
        int slot = atomicAdd(&g_cursor[d], 1);
        g_csrc[slot] = src[e];
    }
}

// ---------------- tiled fp32 GEMM: Y[N,M] = op(X)[N,K] @ W[K,M], row-scaled ----------------
// 256 rows x 64 cols per block, 256 threads, 8x8 microtile, K-chunks of 16.
template <int K, int M, bool PRE>
__global__ __launch_bounds__(256) void k_gemm(const float* __restrict__ X,
                                              const float* __restrict__ W,
                                              float* __restrict__ Y,
                                              const float* __restrict__ bpre) {
    __shared__ __align__(16) float Xs[16][264];  // transposed: Xs[k][row]
    __shared__ __align__(16) float Ws[16][64];

    const int tid  = threadIdx.x;
    const int tx   = tid & 7;     // col group (8 cols)
    const int ty   = tid >> 3;    // row group (8 rows)
    const int row0 = blockIdx.x * 256;

    const int lrow = row0 + tid;  // X-load: one row per thread

    float ndv = 1.0f;
    if (PRE) ndv = (lrow < N_NODES) ? g_nd[lrow] : 0.0f;

    float acc[8][8];
#pragma unroll
    for (int i = 0; i < 8; i++)
#pragma unroll
        for (int j = 0; j < 8; j++) acc[i][j] = 0.0f;

    for (int kc = 0; kc < K; kc += 16) {
        // X tile: 256 rows x 16 k, each thread loads its row's 4 quads
#pragma unroll
        for (int q = 0; q < 4; q++) {
            float4 xv = make_float4(0.f, 0.f, 0.f, 0.f);
            if (lrow < N_NODES)
                xv = *(const float4*)&X[(size_t)lrow * K + kc + q * 4];
            if (PRE) {
                xv.x = fmaxf(fmaf(xv.x, ndv, __ldg(&bpre[kc + q * 4 + 0])), 0.f);
                xv.y = fmaxf(fmaf(xv.y, ndv, __ldg(&bpre[kc + q * 4 + 1])), 0.f);
                xv.z = fmaxf(fmaf(xv.z, ndv, __ldg(&bpre[kc + q * 4 + 2])), 0.f);
                xv.w = fmaxf(fmaf(xv.w, ndv, __ldg(&bpre[kc + q * 4 + 3])), 0.f);
            }
            Xs[q * 4 + 0][tid] = xv.x;
            Xs[q * 4 + 1][tid] = xv.y;
            Xs[q * 4 + 2][tid] = xv.z;
            Xs[q * 4 + 3][tid] = xv.w;
        }
        // W tile: 16 k x 64 cols (zero-padded past M)
        {
            const int wk = tid >> 4;
            const int wc = (tid & 15) * 4;
            float4 wv = make_float4(0.f, 0.f, 0.f, 0.f);
            if (wc < M)
                wv = *(const float4*)&W[(size_t)(kc + wk) * M + wc];
            *(float4*)&Ws[wk][wc] = wv;
        }
        __syncthreads();

#pragma unroll
        for (int k = 0; k < 16; k++) {
            const float4 b0 = *(const float4*)&Ws[k][tx * 8];
            const float4 b1 = *(const float4*)&Ws[k][tx * 8 + 4];
            const float4 a0 = *(const float4*)&Xs[k][ty * 8];
            const float4 a1 = *(const float4*)&Xs[k][ty * 8 + 4];
            const float ar[8] = {a0.x, a0.y, a0.z, a0.w, a1.x, a1.y, a1.z, a1.w};
#pragma unroll
            for (int i = 0; i < 8; i++) {
                acc[i][0] = fmaf(ar[i], b0.x, acc[i][0]);
                acc[i][1] = fmaf(ar[i], b0.y, acc[i][1]);
                acc[i][2] = fmaf(ar[i], b0.z, acc[i][2]);
                acc[i][3] = fmaf(ar[i], b0.w, acc[i][3]);
                acc[i][4] = fmaf(ar[i], b1.x, acc[i][4]);
                acc[i][5] = fmaf(ar[i], b1.y, acc[i][5]);
                acc[i][6] = fmaf(ar[i], b1.z, acc[i][6]);
                acc[i][7] = fmaf(ar[i], b1.w, acc[i][7]);
            }
        }
        __syncthreads();
    }

    const int c = tx * 8;
#pragma unroll
    for (int i = 0; i < 8; i++) {
        const int rr = row0 + ty * 8 + i;
        if (rr < N_NODES && c < M) {
            const float s = g_ns[rr];
            float4 o0, o1;
            o0.x = acc[i][0] * s; o0.y = acc[i][1] * s; o0.z = acc[i][2] * s; o0.w = acc[i][3] * s;
            o1.x = acc[i][4] * s; o1.y = acc[i][5] * s; o1.z = acc[i][6] * s; o1.w = acc[i][7] * s;
            *(float4*)&Y[(size_t)rr * M + c] = o0;
            if (c + 4 < M) *(float4*)&Y[(size_t)rr * M + c + 4] = o1;
        }
    }
}

// ---------------- CSR gather: one warp per node, shfl-broadcast indices ----------------
__global__ __launch_bounds__(256) void k_gather64(const float* __restrict__ xw,
                                                  float* __restrict__ agg) {
    const int node = blockIdx.x * 8 + (threadIdx.x >> 5);
    if (node >= N_NODES) return;
    const int lane = threadIdx.x & 31;
    int       i    = g_rowoff[node];
    const int end  = g_rowoff[node + 1];
    float2 acc = make_float2(0.f, 0.f);
    const size_t fo = (size_t)lane * 2;

    while (end - i >= 32) {
        const int idx = __ldg(&g_csrc[i + lane]);
#pragma unroll
        for (int j = 0; j < 32; j++) {
            const int s = __shfl_sync(0xFFFFFFFFu, idx, j);
            const float2 v = __ldg((const float2*)&xw[(size_t)s * 64 + fo]);
            acc.x += v.x; acc.y += v.y;
        }
        i += 32;
    }
    const int rem = end - i;
    if (rem > 0) {
        const int idx = (lane < rem) ? __ldg(&g_csrc[i + lane]) : 0;
#pragma unroll
        for (int j0 = 0; j0 < 32; j0 += 8) {
            if (j0 >= rem) break;
#pragma unroll
            for (int j = 0; j < 8; j++) {
                const int jj = j0 + j;
                const int s = __shfl_sync(0xFFFFFFFFu, idx, jj);
                if (jj < rem) {
                    const float2 v = __ldg((const float2*)&xw[(size_t)s * 64 + fo]);
                    acc.x += v.x; acc.y += v.y;
                }
            }
        }
    }
    *(float2*)&agg[(size_t)node * 64 + fo] = acc;
}

// 40-wide gather with fused final epilogue: out = sum * nd[node] + b2[col]
__global__ __launch_bounds__(256) void k_gather40(const float* __restrict__ xw,
                                                  float* __restrict__ out,
                                                  const float* __restrict__ b2) {
    const int node = blockIdx.x * 8 + (threadIdx.x >> 5);
    if (node >= N_NODES) return;
    const int lane = threadIdx.x & 31;
    const bool act = (lane < 20);
    int       i    = g_rowoff[node];
    const int end  = g_rowoff[node + 1];
    float2 acc = make_float2(0.f, 0.f);
    const size_t fo = (size_t)lane * 2;

    while (end - i >= 32) {
        const int idx = __ldg(&g_csrc[i + lane]);
#pragma unroll
        for (int j = 0; j < 32; j++) {
            const int s = __shfl_sync(0xFFFFFFFFu, idx, j);
            if (act) {
                const float2 v = __ldg((const float2*)&xw[(size_t)s * F_OUT + fo]);
                acc.x += v.x; acc.y += v.y;
            }
        }
        i += 32;
    }
    const int rem = end - i;
    if (rem > 0) {
        const int idx = (lane < rem) ? __ldg(&g_csrc[i + lane]) : 0;
#pragma unroll
        for (int j0 = 0; j0 < 32; j0 += 8) {
            if (j0 >= rem) break;
#pragma unroll
            for (int j = 0; j < 8; j++) {
                const int jj = j0 + j;
                const int s = __shfl_sync(0xFFFFFFFFu, idx, jj);
                if (act && jj < rem) {
                    const float2 v = __ldg((const float2*)&xw[(size_t)s * F_OUT + fo]);
                    acc.x += v.x; acc.y += v.y;
                }
            }
        }
    }
    if (act) {
        const float nd = g_nd[node];
        float2 o;
        o.x = fmaf(acc.x, nd, __ldg(&b2[fo + 0]));
        o.y = fmaf(acc.y, nd, __ldg(&b2[fo + 1]));
        *(float2*)&out[(size_t)node * F_OUT + fo] = o;
    }
}

// ---------------- host launch ----------------
extern "C" void kernel_launch(void* const* d_in, const int* in_sizes, int n_in,
                              void* d_out, int out_size) {
    (void)in_sizes; (void)n_in; (void)out_size;
    const float* h   = (const float*)d_in[0];
    const float* W0  = (const float*)d_in[1];
    const float* b0  = (const float*)d_in[2];
    const float* W1  = (const float*)d_in[3];
    const float* b1  = (const float*)d_in[4];
    const float* W2  = (const float*)d_in[5];
    const float* b2  = (const float*)d_in[6];
    const int*   src = (const int*)d_in[7];
    const int*   dst = (const int*)d_in[8];
    float* out = (float*)d_out;

    float *pA, *pB, *pC;
    cudaGetSymbolAddress((void**)&pA, g_bufA);
    cudaGetSymbolAddress((void**)&pB, g_bufB);
    cudaGetSymbolAddress((void**)&pC, g_bufC);

    const int nodeBlocks = (N_NODES + 255) / 256;
    const int edgeBlocks = (N_EDGES + 255) / 256;
    const int gemmBlocks = (N_NODES + 255) / 256;
    const int gathBlocks = (N_NODES + 7) / 8;

    // degrees + CSR + norms
    k_zero_deg<<<nodeBlocks, 256>>>();
    k_deg<<<edgeBlocks, 256>>>(src, dst);
    k_scan_block<<<SCAN_NB, SCAN_T>>>();
    k_scan_partials<<<1, 128>>>();
    k_finalize<<<SCAN_NB, SCAN_T>>>();
    k_fill<<<edgeBlocks, 256>>>(src, dst);

    // layer 0
    k_gemm<F_IN, F_HID, false><<<gemmBlocks, 256>>>(h, W0, pA, b0);
    k_gather64<<<gathBlocks, 256>>>(pA, pB);
    // layer 1
    k_gemm<F_HID, F_HID, true><<<gemmBlocks, 256>>>(pB, W1, pA, b0);
    k_gather64<<<gathBlocks, 256>>>(pA, pB);
    // layer 2 (+ fused bias/norm epilogue in gather)
    k_gemm<F_HID, F_OUT, true><<<gemmBlocks, 256>>>(pB, W2, pC, b1);
    k_gather40<<<gathBlocks, 256>>>(pC, out, b2);
}

// round 4
// speedup vs baseline: 1.1943x; 1.1943x over previous
#include <cuda_runtime.h>
#include <cuda_bf16.h>
#include <cstdint>

#define N_NODES 100000
#define N_EDGES 1600000
#define F_IN    128
#define F_HID   64
#define F_OUT   40

#define SCAN_T  1024
#define SCAN_NB ((N_NODES + SCAN_T - 1) / SCAN_T)   // 98

// ---------------- scratch (static device globals; no allocation) ----------------
__device__ int   g_degs_i[N_NODES];
__device__ int   g_degd_i[N_NODES];
__device__ float g_ns[N_NODES];
__device__ float g_nd[N_NODES];
__device__ int   g_incl[N_NODES];
__device__ int   g_rowoff[N_NODES + 1];
__device__ int   g_cursor[N_NODES];
__device__ int   g_partial[SCAN_NB];
__device__ int   g_poff[SCAN_NB];
__device__ int   g_csrc[N_EDGES];
__device__ float g_bufA[(size_t)N_NODES * F_HID];
__device__ float g_bufB[(size_t)N_NODES * F_HID];
__device__ float g_bufC[(size_t)N_NODES * F_OUT];

// ---------------- degree histograms ----------------
__global__ void k_zero_deg() {
    int i = blockIdx.x * blockDim.x + threadIdx.x;
    if (i < N_NODES) { g_degs_i[i] = 0; g_degd_i[i] = 0; }
}

__global__ void k_deg(const int* __restrict__ src, const int* __restrict__ dst) {
    int e = blockIdx.x * blockDim.x + threadIdx.x;
    if (e < N_EDGES) {
        atomicAdd(&g_degs_i[src[e]], 1);
        atomicAdd(&g_degd_i[dst[e]], 1);
    }
}

// ---------------- CSR build ----------------
__global__ __launch_bounds__(SCAN_T) void k_scan_block() {
    __shared__ int ws[32];
    int g = blockIdx.x * SCAN_T + threadIdx.x;
    int lane = threadIdx.x & 31, wid = threadIdx.x >> 5;
    int x = (g < N_NODES) ? g_degd_i[g] : 0;
#pragma unroll
    for (int o = 1; o < 32; o <<= 1) {
        int y = __shfl_up_sync(0xFFFFFFFFu, x, o);
        if (lane >= o) x += y;
    }
    if (lane == 31) ws[wid] = x;
    __syncthreads();
    if (wid == 0) {
        int y = ws[lane];
#pragma unroll
        for (int o = 1; o < 32; o <<= 1) {
            int z = __shfl_up_sync(0xFFFFFFFFu, y, o);
            if (lane >= o) y += z;
        }
        ws[lane] = y;
    }
    __syncthreads();
    int incl = x + (wid > 0 ? ws[wid - 1] : 0);
    if (g < N_NODES) g_incl[g] = incl;
    if (threadIdx.x == SCAN_T - 1) g_partial[blockIdx.x] = incl;
}

// parallel scan of the 98 block partials
__global__ __launch_bounds__(128) void k_scan_partials() {
    __shared__ int ws[4];
    const int t = threadIdx.x;
    const int lane = t & 31, w = t >> 5;
    const int v = (t < SCAN_NB) ? g_partial[t] : 0;
    int x = v;
#pragma unroll
    for (int o = 1; o < 32; o <<= 1) {
        int y = __shfl_up_sync(0xFFFFFFFFu, x, o);
        if (lane >= o) x += y;
    }
    if (lane == 31) ws[w] = x;
    __syncthreads();
    int off = 0;
#pragma unroll
    for (int i = 0; i < 4; i++) if (i < w) off += ws[i];
    if (t < SCAN_NB) g_poff[t] = x + off - v;   // exclusive prefix
}

// finalize rowoff/cursor + both norms
__global__ __launch_bounds__(SCAN_T) void k_finalize() {
    int g = blockIdx.x * SCAN_T + threadIdx.x;
    if (g < N_NODES) {
        int dd   = g_degd_i[g];
        int incl = g_incl[g] + g_poff[blockIdx.x];
        g_rowoff[g + 1] = incl;
        g_cursor[g] = incl - dd;
        if (g == 0) g_rowoff[0] = 0;
        g_ns[g] = rsqrtf(fmaxf((float)g_degs_i[g], 1.0f));
        g_nd[g] = rsqrtf(fmaxf((float)dd, 1.0f));
    }
}

__global__ void k_fill(const int* __restrict__ src, const int* __restrict__ dst) {
    int e = blockIdx.x * blockDim.x + threadIdx.x;
    if (e < N_EDGES) {
        int d = dst[e];
        int slot = atomicAdd(&g_cursor[d], 1);
        g_csrc[slot] = src[e];
    }
}

// ---------------- tiled fp32 GEMM: Y[N,M] = op(X)[N,K] @ W[K,M] ----------------
// 128 rows x 64 cols, 256 threads, 8x4 microtile, K-chunks of 16.
// PRE: x' = relu(x * g_nd[row] + bpre[k]).  SNS: y = acc * g_ns[row] (else y = acc).
template <int K, int M, bool PRE, bool SNS>
__global__ __launch_bounds__(256) void k_gemm(const float* __restrict__ X,
                                              const float* __restrict__ W,
                                              float* __restrict__ Y,
                                              const float* __restrict__ bpre) {
    __shared__ __align__(16) float Xs[16][132];
    __shared__ __align__(16) float Ws[16][64];

    const int tid  = threadIdx.x;
    const int tx   = tid & 15;
    const int ty   = tid >> 4;
    const int row0 = blockIdx.x * 128;

    const int lr   = tid >> 1;
    const int lq   = tid & 1;
    const int lrow = row0 + lr;

    float ndv = 1.0f;
    if (PRE) ndv = (lrow < N_NODES) ? g_nd[lrow] : 0.0f;

    float acc[8][4];
#pragma unroll
    for (int i = 0; i < 8; i++)
#pragma unroll
        for (int j = 0; j < 4; j++) acc[i][j] = 0.0f;

    for (int kc = 0; kc < K; kc += 16) {
#pragma unroll
        for (int q = 0; q < 2; q++) {
            const int kq = lq + q * 2;
            float4 xv = make_float4(0.f, 0.f, 0.f, 0.f);
            if (lrow < N_NODES)
                xv = *(const float4*)&X[(size_t)lrow * K + kc + kq * 4];
            if (PRE) {
                xv.x = fmaxf(fmaf(xv.x, ndv, __ldg(&bpre[kc + kq * 4 + 0])), 0.f);
                xv.y = fmaxf(fmaf(xv.y, ndv, __ldg(&bpre[kc + kq * 4 + 1])), 0.f);
                xv.z = fmaxf(fmaf(xv.z, ndv, __ldg(&bpre[kc + kq * 4 + 2])), 0.f);
                xv.w = fmaxf(fmaf(xv.w, ndv, __ldg(&bpre[kc + kq * 4 + 3])), 0.f);
            }
            Xs[kq * 4 + 0][lr] = xv.x;
            Xs[kq * 4 + 1][lr] = xv.y;
            Xs[kq * 4 + 2][lr] = xv.z;
            Xs[kq * 4 + 3][lr] = xv.w;
        }
        {
            const int wk = tid >> 4;
            const int wc = (tid & 15) * 4;
            float4 wv = make_float4(0.f, 0.f, 0.f, 0.f);
            if (wc < M)
                wv = *(const float4*)&W[(size_t)(kc + wk) * M + wc];
            *(float4*)&Ws[wk][wc] = wv;
        }
        __syncthreads();

#pragma unroll
        for (int k = 0; k < 16; k++) {
            const float4 b  = *(const float4*)&Ws[k][tx * 4];
            const float4 a0 = *(const float4*)&Xs[k][ty * 8];
            const float4 a1 = *(const float4*)&Xs[k][ty * 8 + 4];
            acc[0][0] += a0.x * b.x; acc[0][1] += a0.x * b.y; acc[0][2] += a0.x * b.z; acc[0][3] += a0.x * b.w;
            acc[1][0] += a0.y * b.x; acc[1][1] += a0.y * b.y; acc[1][2] += a0.y * b.z; acc[1][3] += a0.y * b.w;
            acc[2][0] += a0.z * b.x; acc[2][1] += a0.z * b.y; acc[2][2] += a0.z * b.z; acc[2][3] += a0.z * b.w;
            acc[3][0] += a0.w * b.x; acc[3][1] += a0.w * b.y; acc[3][2] += a0.w * b.z; acc[3][3] += a0.w * b.w;
            acc[4][0] += a1.x * b.x; acc[4][1] += a1.x * b.y; acc[4][2] += a1.x * b.z; acc[4][3] += a1.x * b.w;
            acc[5][0] += a1.y * b.x; acc[5][1] += a1.y * b.y; acc[5][2] += a1.y * b.z; acc[5][3] += a1.y * b.w;
            acc[6][0] += a1.z * b.x; acc[6][1] += a1.z * b.y; acc[6][2] += a1.z * b.z; acc[6][3] += a1.z * b.w;
            acc[7][0] += a1.w * b.x; acc[7][1] += a1.w * b.y; acc[7][2] += a1.w * b.z; acc[7][3] += a1.w * b.w;
        }
        __syncthreads();
    }

    const int c = tx * 4;
#pragma unroll
    for (int i = 0; i < 8; i++) {
        const int rr = row0 + ty * 8 + i;
        if (rr < N_NODES && c < M) {
            const float s = SNS ? g_ns[rr] : 1.0f;
            float4 o;
            o.x = acc[i][0] * s; o.y = acc[i][1] * s;
            o.z = acc[i][2] * s; o.w = acc[i][3] * s;
            *(float4*)&Y[(size_t)rr * M + c] = o;
        }
    }
}

// ---------------- CSR gather: 16 threads per node, float4, unroll 4 ----------------
// ESCALE: per-edge multiply by g_ns[src] (used when the GEMM skipped its ns epilogue).
template <bool ESCALE>
__global__ __launch_bounds__(256) void k_gather64(const float* __restrict__ xw,
                                                  float* __restrict__ agg) {
    const int node = blockIdx.x * 16 + (threadIdx.x >> 4);
    if (node >= N_NODES) return;
    const int f   = (threadIdx.x & 15) << 2;
    int       i   = g_rowoff[node];
    const int end = g_rowoff[node + 1];
    float4 acc = make_float4(0.f, 0.f, 0.f, 0.f);
    for (; i + 3 < end; i += 4) {
        const int s0 = __ldg(&g_csrc[i + 0]);
        const int s1 = __ldg(&g_csrc[i + 1]);
        const int s2 = __ldg(&g_csrc[i + 2]);
        const int s3 = __ldg(&g_csrc[i + 3]);
        float n0 = 1.f, n1 = 1.f, n2 = 1.f, n3 = 1.f;
        if (ESCALE) {
            n0 = __ldg(&g_ns[s0]); n1 = __ldg(&g_ns[s1]);
            n2 = __ldg(&g_ns[s2]); n3 = __ldg(&g_ns[s3]);
        }
        const float4 v0 = __ldg((const float4*)&xw[(size_t)s0 * 64 + f]);
        const float4 v1 = __ldg((const float4*)&xw[(size_t)s1 * 64 + f]);
        const float4 v2 = __ldg((const float4*)&xw[(size_t)s2 * 64 + f]);
        const float4 v3 = __ldg((const float4*)&xw[(size_t)s3 * 64 + f]);
        if (ESCALE) {
            acc.x = fmaf(v0.x, n0, fmaf(v1.x, n1, fmaf(v2.x, n2, fmaf(v3.x, n3, acc.x))));
            acc.y = fmaf(v0.y, n0, fmaf(v1.y, n1, fmaf(v2.y, n2, fmaf(v3.y, n3, acc.y))));
            acc.z = fmaf(v0.z, n0, fmaf(v1.z, n1, fmaf(v2.z, n2, fmaf(v3.z, n3, acc.z))));
            acc.w = fmaf(v0.w, n0, fmaf(v1.w, n1, fmaf(v2.w, n2, fmaf(v3.w, n3, acc.w))));
        } else {
            acc.x += v0.x + v1.x + v2.x + v3.x;
            acc.y += v0.y + v1.y + v2.y + v3.y;
            acc.z += v0.z + v1.z + v2.z + v3.z;
            acc.w += v0.w + v1.w + v2.w + v3.w;
        }
    }
    for (; i < end; i++) {
        const int s = __ldg(&g_csrc[i]);
        const float n = ESCALE ? __ldg(&g_ns[s]) : 1.0f;
        const float4 v = __ldg((const float4*)&xw[(size_t)s * 64 + f]);
        acc.x = fmaf(v.x, n, acc.x); acc.y = fmaf(v.y, n, acc.y);
        acc.z = fmaf(v.z, n, acc.z); acc.w = fmaf(v.w, n, acc.w);
    }
    *(float4*)&agg[(size_t)node * 64 + f] = acc;
}

// 40-wide gather with fused final epilogue: out = sum * nd[node] + b2[col]
__global__ __launch_bounds__(256) void k_gather40(const float* __restrict__ xw,
                                                  float* __restrict__ out,
                                                  const float* __restrict__ b2) {
    const int node = blockIdx.x * 16 + (threadIdx.x >> 4);
    if (node >= N_NODES) return;
    const int f = (threadIdx.x & 15) << 2;
    if (f >= F_OUT) return;
    int       i   = g_rowoff[node];
    const int end = g_rowoff[node + 1];
    float4 acc = make_float4(0.f, 0.f, 0.f, 0.f);
    for (; i + 3 < end; i += 4) {
        const int s0 = __ldg(&g_csrc[i + 0]);
        const int s1 = __ldg(&g_csrc[i + 1]);
        const int s2 = __ldg(&g_csrc[i + 2]);
        const int s3 = __ldg(&g_csrc[i + 3]);
        const float4 v0 = __ldg((const float4*)&xw[(size_t)s0 * F_OUT + f]);
        const float4 v1 = __ldg((const float4*)&xw[(size_t)s1 * F_OUT + f]);
        const float4 v2 = __ldg((const float4*)&xw[(size_t)s2 * F_OUT + f]);
        const float4 v3 = __ldg((const float4*)&xw[(size_t)s3 * F_OUT + f]);
        acc.x += v0.x + v1.x + v2.x + v3.x;
        acc.y += v0.y + v1.y + v2.y + v3.y;
        acc.z += v0.z + v1.z + v2.z + v3.z;
        acc.w += v0.w + v1.w + v2.w + v3.w;
    }
    for (; i < end; i++) {
        const int s = __ldg(&g_csrc[i]);
        const float4 v = __ldg((const float4*)&xw[(size_t)s * F_OUT + f]);
        acc.x += v.x; acc.y += v.y; acc.z += v.z; acc.w += v.w;
    }
    const float nd = g_nd[node];
    float4 o;
    o.x = fmaf(acc.x, nd, __ldg(&b2[f + 0]));
    o.y = fmaf(acc.y, nd, __ldg(&b2[f + 1]));
    o.z = fmaf(acc.z, nd, __ldg(&b2[f + 2]));
    o.w = fmaf(acc.w, nd, __ldg(&b2[f + 3]));
    *(float4*)&out[(size_t)node * F_OUT + f] = o;
}

// ---------------- host launch ----------------
extern "C" void kernel_launch(void* const* d_in, const int* in_sizes, int n_in,
                              void* d_out, int out_size) {
    (void)in_sizes; (void)n_in; (void)out_size;
    const float* h   = (const float*)d_in[0];
    const float* W0  = (const float*)d_in[1];
    const float* b0  = (const float*)d_in[2];
    const float* W1  = (const float*)d_in[3];
    const float* b1  = (const float*)d_in[4];
    const float* W2  = (const float*)d_in[5];
    const float* b2  = (const float*)d_in[6];
    const int*   src = (const int*)d_in[7];
    const int*   dst = (const int*)d_in[8];
    float* out = (float*)d_out;

    float *pA, *pB, *pC;
    cudaGetSymbolAddress((void**)&pA, g_bufA);
    cudaGetSymbolAddress((void**)&pB, g_bufB);
    cudaGetSymbolAddress((void**)&pC, g_bufC);

    // one-time side stream + events for the capture fork (host objects, not device mem)
    static cudaStream_t s2 = []() {
        cudaStream_t s; cudaStreamCreateWithFlags(&s, cudaStreamNonBlocking); return s;
    }();
    static cudaEvent_t evFork = []() {
        cudaEvent_t e; cudaEventCreateWithFlags(&e, cudaEventDisableTiming); return e;
    }();
    static cudaEvent_t evJoin = []() {
        cudaEvent_t e; cudaEventCreateWithFlags(&e, cudaEventDisableTiming); return e;
    }();

    const int nodeBlocks = (N_NODES + 255) / 256;
    const int edgeBlocks = (N_EDGES + 255) / 256;
    const int gemmBlocks = (N_NODES + 127) / 128;
    const int gathBlocks = (N_NODES + 15) / 16;

    // ---- fork: GEMM0 (graph-independent; ns applied later per-edge) on s2 ----
    cudaEventRecord(evFork, 0);
    cudaStreamWaitEvent(s2, evFork, 0);
    k_gemm<F_IN, F_HID, false, false><<<gemmBlocks, 256, 0, s2>>>(h, W0, pA, b0);
    cudaEventRecord(evJoin, s2);

    // ---- main stream: degrees + CSR + norms ----
    k_zero_deg<<<nodeBlocks, 256>>>();
    k_deg<<<edgeBlocks, 256>>>(src, dst);
    k_scan_block<<<SCAN_NB, SCAN_T>>>();
    k_scan_partials<<<1, 128>>>();
    k_finalize<<<SCAN_NB, SCAN_T>>>();
    k_fill<<<edgeBlocks, 256>>>(src, dst);

    // ---- join, then layer 0 gather (applies ns[src] per edge) ----
    cudaStreamWaitEvent(0, evJoin, 0);
    k_gather64<true><<<gathBlocks, 256>>>(pA, pB);

    // layer 1
    k_gemm<F_HID, F_HID, true, true><<<gemmBlocks, 256>>>(pB, W1, pA, b0);
    k_gather64<false><<<gathBlocks, 256>>>(pA, pB);

    // layer 2 (+ fused bias/norm epilogue in gather)
    k_gemm<F_HID, F_OUT, true, true><<<gemmBlocks, 256>>>(pB, W2, pC, b1);
    k_gather40<<<gathBlocks, 256>>>(pC, out, b2);
}

// round 5
// speedup vs baseline: 1.3143x; 1.1005x over previous
#include <cuda_runtime.h>
#include <cuda_fp16.h>
#include <cstdint>

#define N_NODES 100000
#define N_EDGES 1600000
#define F_IN    128
#define F_HID   64
#define F_OUT   40

#define SCAN_T  1024
#define SCAN_NB ((N_NODES + SCAN_T - 1) / SCAN_T)   // 98

// ---------------- scratch (static device globals; no allocation) ----------------
__device__ int    g_degs_i[N_NODES];
__device__ int    g_degd_i[N_NODES];
__device__ float  g_ns[N_NODES];
__device__ float  g_nd[N_NODES];
__device__ int    g_incl[N_NODES];
__device__ int    g_rowoff[N_NODES + 1];
__device__ int    g_cursor[N_NODES];
__device__ int    g_partial[SCAN_NB];
__device__ int    g_poff[SCAN_NB];
__device__ int    g_csrc[N_EDGES];
__device__ __half g_xw64[(size_t)N_NODES * F_HID];   // GEMM output, fp16 (gather input)
__device__ __half g_xw40[(size_t)N_NODES * F_OUT];   // layer-2 GEMM output, fp16
__device__ float  g_agg [(size_t)N_NODES * F_HID];   // gather output, fp32

// ---------------- degree histograms (split: dst on critical path) ----------------
__global__ void k_zero_deg() {
    int i = blockIdx.x * blockDim.x + threadIdx.x;
    if (i < N_NODES) { g_degs_i[i] = 0; g_degd_i[i] = 0; }
}

__global__ void k_deg_dst(const int* __restrict__ dst) {
    int e = blockIdx.x * blockDim.x + threadIdx.x;
    if (e < N_EDGES) atomicAdd(&g_degd_i[dst[e]], 1);
}

__global__ void k_deg_src(const int* __restrict__ src) {
    int e = blockIdx.x * blockDim.x + threadIdx.x;
    if (e < N_EDGES) atomicAdd(&g_degs_i[src[e]], 1);
}

__global__ void k_ns() {
    int i = blockIdx.x * blockDim.x + threadIdx.x;
    if (i < N_NODES) g_ns[i] = rsqrtf(fmaxf((float)g_degs_i[i], 1.0f));
}

// ---------------- CSR build ----------------
__global__ __launch_bounds__(SCAN_T) void k_scan_block() {
    __shared__ int ws[32];
    int g = blockIdx.x * SCAN_T + threadIdx.x;
    int lane = threadIdx.x & 31, wid = threadIdx.x >> 5;
    int x = (g < N_NODES) ? g_degd_i[g] : 0;
#pragma unroll
    for (int o = 1; o < 32; o <<= 1) {
        int y = __shfl_up_sync(0xFFFFFFFFu, x, o);
        if (lane >= o) x += y;
    }
    if (lane == 31) ws[wid] = x;
    __syncthreads();
    if (wid == 0) {
        int y = ws[lane];
#pragma unroll
        for (int o = 1; o < 32; o <<= 1) {
            int z = __shfl_up_sync(0xFFFFFFFFu, y, o);
            if (lane >= o) y += z;
        }
        ws[lane] = y;
    }
    __syncthreads();
    int incl = x + (wid > 0 ? ws[wid - 1] : 0);
    if (g < N_NODES) g_incl[g] = incl;
    if (threadIdx.x == SCAN_T - 1) g_partial[blockIdx.x] = incl;
}

__global__ __launch_bounds__(128) void k_scan_partials() {
    __shared__ int ws[4];
    const int t = threadIdx.x;
    const int lane = t & 31, w = t >> 5;
    const int v = (t < SCAN_NB) ? g_partial[t] : 0;
    int x = v;
#pragma unroll
    for (int o = 1; o < 32; o <<= 1) {
        int y = __shfl_up_sync(0xFFFFFFFFu, x, o);
        if (lane >= o) x += y;
    }
    if (lane == 31) ws[w] = x;
    __syncthreads();
    int off = 0;
#pragma unroll
    for (int i = 0; i < 4; i++) if (i < w) off += ws[i];
    if (t < SCAN_NB) g_poff[t] = x + off - v;   // exclusive prefix
}

// finalize rowoff/cursor + nd norm
__global__ __launch_bounds__(SCAN_T) void k_finalize() {
    int g = blockIdx.x * SCAN_T + threadIdx.x;
    if (g < N_NODES) {
        int dd   = g_degd_i[g];
        int incl = g_incl[g] + g_poff[blockIdx.x];
        g_rowoff[g + 1] = incl;
        g_cursor[g] = incl - dd;
        if (g == 0) g_rowoff[0] = 0;
        g_nd[g] = rsqrtf(fmaxf((float)dd, 1.0f));
    }
}

__global__ void k_fill(const int* __restrict__ src, const int* __restrict__ dst) {
    int e = blockIdx.x * blockDim.x + threadIdx.x;
    if (e < N_EDGES) {
        int d = dst[e];
        int slot = atomicAdd(&g_cursor[d], 1);
        g_csrc[slot] = src[e];
    }
}

// ---------------- tiled fp32 GEMM -> fp16 output ----------------
// 128 rows x 64 cols, 256 threads, 8x4 microtile, K-chunks of 16.
// PRE: x' = relu(x * g_nd[row] + bpre[k]).  SNS: y = acc * g_ns[row].
template <int K, int M, bool PRE, bool SNS>
__global__ __launch_bounds__(256) void k_gemm(const float* __restrict__ X,
                                              const float* __restrict__ W,
                                              __half* __restrict__ Y,
                                              const float* __restrict__ bpre) {
    __shared__ __align__(16) float Xs[16][132];
    __shared__ __align__(16) float Ws[16][64];

    const int tid  = threadIdx.x;
    const int tx   = tid & 15;
    const int ty   = tid >> 4;
    const int row0 = blockIdx.x * 128;

    const int lr   = tid >> 1;
    const int lq   = tid & 1;
    const int lrow = row0 + lr;

    float ndv = 1.0f;
    if (PRE) ndv = (lrow < N_NODES) ? g_nd[lrow] : 0.0f;

    float acc[8][4];
#pragma unroll
    for (int i = 0; i < 8; i++)
#pragma unroll
        for (int j = 0; j < 4; j++) acc[i][j] = 0.0f;

    for (int kc = 0; kc < K; kc += 16) {
#pragma unroll
        for (int q = 0; q < 2; q++) {
            const int kq = lq + q * 2;
            float4 xv = make_float4(0.f, 0.f, 0.f, 0.f);
            if (lrow < N_NODES)
                xv = *(const float4*)&X[(size_t)lrow * K + kc + kq * 4];
            if (PRE) {
                xv.x = fmaxf(fmaf(xv.x, ndv, __ldg(&bpre[kc + kq * 4 + 0])), 0.f);
                xv.y = fmaxf(fmaf(xv.y, ndv, __ldg(&bpre[kc + kq * 4 + 1])), 0.f);
                xv.z = fmaxf(fmaf(xv.z, ndv, __ldg(&bpre[kc + kq * 4 + 2])), 0.f);
                xv.w = fmaxf(fmaf(xv.w, ndv, __ldg(&bpre[kc + kq * 4 + 3])), 0.f);
            }
            Xs[kq * 4 + 0][lr] = xv.x;
            Xs[kq * 4 + 1][lr] = xv.y;
            Xs[kq * 4 + 2][lr] = xv.z;
            Xs[kq * 4 + 3][lr] = xv.w;
        }
        {
            const int wk = tid >> 4;
            const int wc = (tid & 15) * 4;
            float4 wv = make_float4(0.f, 0.f, 0.f, 0.f);
            if (wc < M)
                wv = *(const float4*)&W[(size_t)(kc + wk) * M + wc];
            *(float4*)&Ws[wk][wc] = wv;
        }
        __syncthreads();

#pragma unroll
        for (int k = 0; k < 16; k++) {
            const float4 b  = *(const float4*)&Ws[k][tx * 4];
            const float4 a0 = *(const float4*)&Xs[k][ty * 8];
            const float4 a1 = *(const float4*)&Xs[k][ty * 8 + 4];
            acc[0][0] += a0.x * b.x; acc[0][1] += a0.x * b.y; acc[0][2] += a0.x * b.z; acc[0][3] += a0.x * b.w;
            acc[1][0] += a0.y * b.x; acc[1][1] += a0.y * b.y; acc[1][2] += a0.y * b.z; acc[1][3] += a0.y * b.w;
            acc[2][0] += a0.z * b.x; acc[2][1] += a0.z * b.y; acc[2][2] += a0.z * b.z; acc[2][3] += a0.z * b.w;
            acc[3][0] += a0.w * b.x; acc[3][1] += a0.w * b.y; acc[3][2] += a0.w * b.z; acc[3][3] += a0.w * b.w;
            acc[4][0] += a1.x * b.x; acc[4][1] += a1.x * b.y; acc[4][2] += a1.x * b.z; acc[4][3] += a1.x * b.w;
            acc[5][0] += a1.y * b.x; acc[5][1] += a1.y * b.y; acc[5][2] += a1.y * b.z; acc[5][3] += a1.y * b.w;
            acc[6][0] += a1.z * b.x; acc[6][1] += a1.z * b.y; acc[6][2] += a1.z * b.z; acc[6][3] += a1.z * b.w;
            acc[7][0] += a1.w * b.x; acc[7][1] += a1.w * b.y; acc[7][2] += a1.w * b.z; acc[7][3] += a1.w * b.w;
        }
        __syncthreads();
    }

    const int c = tx * 4;
#pragma unroll
    for (int i = 0; i < 8; i++) {
        const int rr = row0 + ty * 8 + i;
        if (rr < N_NODES && c < M) {
            const float s = SNS ? g_ns[rr] : 1.0f;
            union { uint2 u; __half2 h[2]; } p;
            p.h[0] = __floats2half2_rn(acc[i][0] * s, acc[i][1] * s);
            p.h[1] = __floats2half2_rn(acc[i][2] * s, acc[i][3] * s);
            *(uint2*)&Y[(size_t)rr * M + c] = p.u;   // 8B aligned: M,c multiples of 4
        }
    }
}

// ---------------- CSR gather (fp16 features, fp32 accum): 16 thr/node ----------------
__device__ __forceinline__ void h4_acc(float4& acc, uint2 raw, float n) {
    union { uint2 u; __half2 h[2]; } p; p.u = raw;
    const float2 a = __half22float2(p.h[0]);
    const float2 b = __half22float2(p.h[1]);
    acc.x = fmaf(a.x, n, acc.x); acc.y = fmaf(a.y, n, acc.y);
    acc.z = fmaf(b.x, n, acc.z); acc.w = fmaf(b.y, n, acc.w);
}

template <bool ESCALE>
__global__ __launch_bounds__(256) void k_gather64(const __half* __restrict__ xw,
                                                  float* __restrict__ agg) {
    const int node = blockIdx.x * 16 + (threadIdx.x >> 4);
    if (node >= N_NODES) return;
    const int f   = (threadIdx.x & 15) << 2;
    int       i   = g_rowoff[node];
    const int end = g_rowoff[node + 1];
    float4 acc = make_float4(0.f, 0.f, 0.f, 0.f);
    for (; i + 3 < end; i += 4) {
        const int s0 = __ldg(&g_csrc[i + 0]);
        const int s1 = __ldg(&g_csrc[i + 1]);
        const int s2 = __ldg(&g_csrc[i + 2]);
        const int s3 = __ldg(&g_csrc[i + 3]);
        float n0 = 1.f, n1 = 1.f, n2 = 1.f, n3 = 1.f;
        if (ESCALE) {
            n0 = __ldg(&g_ns[s0]); n1 = __ldg(&g_ns[s1]);
            n2 = __ldg(&g_ns[s2]); n3 = __ldg(&g_ns[s3]);
        }
        const uint2 r0 = __ldg((const uint2*)&xw[(size_t)s0 * 64 + f]);
        const uint2 r1 = __ldg((const uint2*)&xw[(size_t)s1 * 64 + f]);
        const uint2 r2 = __ldg((const uint2*)&xw[(size_t)s2 * 64 + f]);
        const uint2 r3 = __ldg((const uint2*)&xw[(size_t)s3 * 64 + f]);
        h4_acc(acc, r0, n0); h4_acc(acc, r1, n1);
        h4_acc(acc, r2, n2); h4_acc(acc, r3, n3);
    }
    for (; i < end; i++) {
        const int s = __ldg(&g_csrc[i]);
        const float n = ESCALE ? __ldg(&g_ns[s]) : 1.0f;
        h4_acc(acc, __ldg((const uint2*)&xw[(size_t)s * 64 + f]), n);
    }
    *(float4*)&agg[(size_t)node * 64 + f] = acc;
}

// 40-wide fp16 gather with fused final epilogue: out = sum * nd[node] + b2[col]
__global__ __launch_bounds__(256) void k_gather40(const __half* __restrict__ xw,
                                                  float* __restrict__ out,
                                                  const float* __restrict__ b2) {
    const int node = blockIdx.x * 16 + (threadIdx.x >> 4);
    if (node >= N_NODES) return;
    const int f = (threadIdx.x & 15) << 2;
    if (f >= F_OUT) return;
    int       i   = g_rowoff[node];
    const int end = g_rowoff[node + 1];
    float4 acc = make_float4(0.f, 0.f, 0.f, 0.f);
    for (; i + 3 < end; i += 4) {
        const int s0 = __ldg(&g_csrc[i + 0]);
        const int s1 = __ldg(&g_csrc[i + 1]);
        const int s2 = __ldg(&g_csrc[i + 2]);
        const int s3 = __ldg(&g_csrc[i + 3]);
        h4_acc(acc, __ldg((const uint2*)&xw[(size_t)s0 * F_OUT + f]), 1.f);
        h4_acc(acc, __ldg((const uint2*)&xw[(size_t)s1 * F_OUT + f]), 1.f);
        h4_acc(acc, __ldg((const uint2*)&xw[(size_t)s2 * F_OUT + f]), 1.f);
        h4_acc(acc, __ldg((const uint2*)&xw[(size_t)s3 * F_OUT + f]), 1.f);
    }
    for (; i < end; i++) {
        const int s = __ldg(&g_csrc[i]);
        h4_acc(acc, __ldg((const uint2*)&xw[(size_t)s * F_OUT + f]), 1.f);
    }
    const float nd = g_nd[node];
    float4 o;
    o.x = fmaf(acc.x, nd, __ldg(&b2[f + 0]));
    o.y = fmaf(acc.y, nd, __ldg(&b2[f + 1]));
    o.z = fmaf(acc.z, nd, __ldg(&b2[f + 2]));
    o.w = fmaf(acc.w, nd, __ldg(&b2[f + 3]));
    *(float4*)&out[(size_t)node * F_OUT + f] = o;
}

// ---------------- host launch ----------------
extern "C" void kernel_launch(void* const* d_in, const int* in_sizes, int n_in,
                              void* d_out, int out_size) {
    (void)in_sizes; (void)n_in; (void)out_size;
    const float* h   = (const float*)d_in[0];
    const float* W0  = (const float*)d_in[1];
    const float* b0  = (const float*)d_in[2];
    const float* W1  = (const float*)d_in[3];
    const float* b1  = (const float*)d_in[4];
    const float* W2  = (const float*)d_in[5];
    const float* b2  = (const float*)d_in[6];
    const int*   src = (const int*)d_in[7];
    const int*   dst = (const int*)d_in[8];
    float* out = (float*)d_out;

    __half *pXW64, *pXW40;
    float  *pAgg;
    cudaGetSymbolAddress((void**)&pXW64, g_xw64);
    cudaGetSymbolAddress((void**)&pXW40, g_xw40);
    cudaGetSymbolAddress((void**)&pAgg,  g_agg);

    static cudaStream_t s2 = []() {
        cudaStream_t s; cudaStreamCreateWithFlags(&s, cudaStreamNonBlocking); return s;
    }();
    static cudaEvent_t evFork = []() {
        cudaEvent_t e; cudaEventCreateWithFlags(&e, cudaEventDisableTiming); return e;
    }();
    static cudaEvent_t evJoin = []() {
        cudaEvent_t e; cudaEventCreateWithFlags(&e, cudaEventDisableTiming); return e;
    }();

    const int nodeBlocks = (N_NODES + 255) / 256;
    const int edgeBlocks = (N_EDGES + 255) / 256;
    const int gemmBlocks = (N_NODES + 127) / 128;
    const int gathBlocks = (N_NODES + 15) / 16;

    // ---- main: zero degrees, then fork ----
    k_zero_deg<<<nodeBlocks, 256>>>();
    cudaEventRecord(evFork, 0);

    // ---- side stream: GEMM0 + src-degree histogram + ns ----
    cudaStreamWaitEvent(s2, evFork, 0);
    k_gemm<F_IN, F_HID, false, false><<<gemmBlocks, 256, 0, s2>>>(h, W0, pXW64, b0);
    k_deg_src<<<edgeBlocks, 256, 0, s2>>>(src);
    k_ns<<<nodeBlocks, 256, 0, s2>>>();
    cudaEventRecord(evJoin, s2);

    // ---- main: dst histogram + CSR ----
    k_deg_dst<<<edgeBlocks, 256>>>(dst);
    k_scan_block<<<SCAN_NB, SCAN_T>>>();
    k_scan_partials<<<1, 128>>>();
    k_finalize<<<SCAN_NB, SCAN_T>>>();
    k_fill<<<edgeBlocks, 256>>>(src, dst);

    // ---- join, layer-0 gather (ns applied per edge) ----
    cudaStreamWaitEvent(0, evJoin, 0);
    k_gather64<true><<<gathBlocks, 256>>>(pXW64, pAgg);

    // layer 1
    k_gemm<F_HID, F_HID, true, true><<<gemmBlocks, 256>>>(pAgg, W1, pXW64, b0);
    k_gather64<false><<<gathBlocks, 256>>>(pXW64, pAgg);

    // layer 2 (+ fused bias/norm epilogue in gather)
    k_gemm<F_HID, F_OUT, true, true><<<gemmBlocks, 256>>>(pAgg, W2, pXW40, b1);
    k_gather40<<<gathBlocks, 256>>>(pXW40, out, b2);
}

// round 6
// speedup vs baseline: 1.3274x; 1.0100x over previous
#include <cuda_runtime.h>
#include <cuda_fp16.h>
#include <cstdint>

#define N_NODES 100000
#define N_EDGES 1600000
#define F_IN    128
#define F_HID   64
#define F_OUT   40

#define SCAN_T  1024
#define SCAN_NB ((N_NODES + SCAN_T - 1) / SCAN_T)   // 98

// ---------------- scratch (static device globals; no allocation) ----------------
__device__ int    g_degs_i[N_NODES];
__device__ int    g_degd_i[N_NODES];
__device__ float  g_ns[N_NODES];
__device__ float  g_nd[N_NODES];
__device__ int    g_incl[N_NODES];
__device__ int    g_rowoff[N_NODES + 1];
__device__ int    g_cursor[N_NODES];
__device__ int    g_partial[SCAN_NB];
__device__ int    g_csrc[N_EDGES];
__device__ __half g_xw64[(size_t)N_NODES * F_HID];
__device__ __half g_xw40[(size_t)N_NODES * F_OUT];
__device__ float  g_agg [(size_t)N_NODES * F_HID];

// ---------------- zero both degree arrays (int4) ----------------
__global__ void k_zero_deg() {
    int i = blockIdx.x * blockDim.x + threadIdx.x;
    const int n4 = N_NODES / 4;      // 25000
    if (i < n4) {
        ((int4*)g_degs_i)[i] = make_int4(0, 0, 0, 0);
        ((int4*)g_degd_i)[i] = make_int4(0, 0, 0, 0);
    }
}

// ---------------- degree histograms (4 edges per thread) ----------------
__global__ void k_deg_dst(const int* __restrict__ dst) {
    int i = blockIdx.x * blockDim.x + threadIdx.x;
    if (i < N_EDGES / 4) {
        const int4 d = __ldg(&((const int4*)dst)[i]);
        atomicAdd(&g_degd_i[d.x], 1);
        atomicAdd(&g_degd_i[d.y], 1);
        atomicAdd(&g_degd_i[d.z], 1);
        atomicAdd(&g_degd_i[d.w], 1);
    }
}

__global__ void k_deg_src(const int* __restrict__ src) {
    int i = blockIdx.x * blockDim.x + threadIdx.x;
    if (i < N_EDGES / 4) {
        const int4 s = __ldg(&((const int4*)src)[i]);
        atomicAdd(&g_degs_i[s.x], 1);
        atomicAdd(&g_degs_i[s.y], 1);
        atomicAdd(&g_degs_i[s.z], 1);
        atomicAdd(&g_degs_i[s.w], 1);
    }
}

__global__ void k_ns() {
    int i = blockIdx.x * blockDim.x + threadIdx.x;
    if (i < N_NODES) g_ns[i] = rsqrtf(fmaxf((float)g_degs_i[i], 1.0f));
}

// ---------------- CSR build ----------------
__global__ __launch_bounds__(SCAN_T) void k_scan_block() {
    __shared__ int ws[32];
    int g = blockIdx.x * SCAN_T + threadIdx.x;
    int lane = threadIdx.x & 31, wid = threadIdx.x >> 5;
    int x = (g < N_NODES) ? g_degd_i[g] : 0;
#pragma unroll
    for (int o = 1; o < 32; o <<= 1) {
        int y = __shfl_up_sync(0xFFFFFFFFu, x, o);
        if (lane >= o) x += y;
    }
    if (lane == 31) ws[wid] = x;
    __syncthreads();
    if (wid == 0) {
        int y = ws[lane];
#pragma unroll
        for (int o = 1; o < 32; o <<= 1) {
            int z = __shfl_up_sync(0xFFFFFFFFu, y, o);
            if (lane >= o) y += z;
        }
        ws[lane] = y;
    }
    __syncthreads();
    int incl = x + (wid > 0 ? ws[wid - 1] : 0);
    if (g < N_NODES) g_incl[g] = incl;
    if (threadIdx.x == SCAN_T - 1) g_partial[blockIdx.x] = incl;
}

// finalize: per-block recompute of the partials prefix (no separate scan_partials launch)
__global__ __launch_bounds__(SCAN_T) void k_finalize() {
    __shared__ int ws[32];
    __shared__ int s_off;
    const int tid = threadIdx.x;
    const int lane = tid & 31, w = tid >> 5;

    // offset = sum of g_partial[j] for j < blockIdx.x (masked parallel reduction)
    int v = 0;
    if (tid < SCAN_NB && tid < blockIdx.x) v = g_partial[tid];
#pragma unroll
    for (int o = 16; o > 0; o >>= 1) v += __shfl_down_sync(0xFFFFFFFFu, v, o);
    if (tid < 128) {                 // partials fit in first 4 warps (98 < 128)
        if (lane == 0) ws[w] = v;
    }
    __syncthreads();
    if (tid == 0) s_off = ws[0] + ws[1] + ws[2] + ws[3];
    __syncthreads();
    const int off = s_off;

    int g = blockIdx.x * SCAN_T + tid;
    if (g < N_NODES) {
        int dd   = g_degd_i[g];
        int incl = g_incl[g] + off;
        g_rowoff[g + 1] = incl;
        g_cursor[g] = incl - dd;
        if (g == 0) g_rowoff[0] = 0;
        g_nd[g] = rsqrtf(fmaxf((float)dd, 1.0f));
    }
}

// fill: 4 edges per thread
__global__ void k_fill(const int* __restrict__ src, const int* __restrict__ dst) {
    int i = blockIdx.x * blockDim.x + threadIdx.x;
    if (i < N_EDGES / 4) {
        const int4 s = __ldg(&((const int4*)src)[i]);
        const int4 d = __ldg(&((const int4*)dst)[i]);
        g_csrc[atomicAdd(&g_cursor[d.x], 1)] = s.x;
        g_csrc[atomicAdd(&g_cursor[d.y], 1)] = s.y;
        g_csrc[atomicAdd(&g_cursor[d.z], 1)] = s.z;
        g_csrc[atomicAdd(&g_cursor[d.w], 1)] = s.w;
    }
}

// ---------------- tiled fp32 GEMM -> fp16 output ----------------
// 128 rows x 64 cols, 256 threads, 8x4 microtile, K-chunks of 16.
template <int K, int M, bool PRE, bool SNS>
__global__ __launch_bounds__(256) void k_gemm(const float* __restrict__ X,
                                              const float* __restrict__ W,
                                              __half* __restrict__ Y,
                                              const float* __restrict__ bpre) {
    __shared__ __align__(16) float Xs[16][132];
    __shared__ __align__(16) float Ws[16][64];

    const int tid  = threadIdx.x;
    const int tx   = tid & 15;
    const int ty   = tid >> 4;
    const int row0 = blockIdx.x * 128;

    const int lr   = tid >> 1;
    const int lq   = tid & 1;
    const int lrow = row0 + lr;

    float ndv = 1.0f;
    if (PRE) ndv = (lrow < N_NODES) ? g_nd[lrow] : 0.0f;

    float acc[8][4];
#pragma unroll
    for (int i = 0; i < 8; i++)
#pragma unroll
        for (int j = 0; j < 4; j++) acc[i][j] = 0.0f;

    for (int kc = 0; kc < K; kc += 16) {
#pragma unroll
        for (int q = 0; q < 2; q++) {
            const int kq = lq + q * 2;
            float4 xv = make_float4(0.f, 0.f, 0.f, 0.f);
            if (lrow < N_NODES)
                xv = *(const float4*)&X[(size_t)lrow * K + kc + kq * 4];
            if (PRE) {
                xv.x = fmaxf(fmaf(xv.x, ndv, __ldg(&bpre[kc + kq * 4 + 0])), 0.f);
                xv.y = fmaxf(fmaf(xv.y, ndv, __ldg(&bpre[kc + kq * 4 + 1])), 0.f);
                xv.z = fmaxf(fmaf(xv.z, ndv, __ldg(&bpre[kc + kq * 4 + 2])), 0.f);
                xv.w = fmaxf(fmaf(xv.w, ndv, __ldg(&bpre[kc + kq * 4 + 3])), 0.f);
            }
            Xs[kq * 4 + 0][lr] = xv.x;
            Xs[kq * 4 + 1][lr] = xv.y;
            Xs[kq * 4 + 2][lr] = xv.z;
            Xs[kq * 4 + 3][lr] = xv.w;
        }
        {
            const int wk = tid >> 4;
            const int wc = (tid & 15) * 4;
            float4 wv = make_float4(0.f, 0.f, 0.f, 0.f);
            if (wc < M)
                wv = *(const float4*)&W[(size_t)(kc + wk) * M + wc];
            *(float4*)&Ws[wk][wc] = wv;
        }
        __syncthreads();

#pragma unroll
        for (int k = 0; k < 16; k++) {
            const float4 b  = *(const float4*)&Ws[k][tx * 4];
            const float4 a0 = *(const float4*)&Xs[k][ty * 8];
            const float4 a1 = *(const float4*)&Xs[k][ty * 8 + 4];
            acc[0][0] += a0.x * b.x; acc[0][1] += a0.x * b.y; acc[0][2] += a0.x * b.z; acc[0][3] += a0.x * b.w;
            acc[1][0] += a0.y * b.x; acc[1][1] += a0.y * b.y; acc[1][2] += a0.y * b.z; acc[1][3] += a0.y * b.w;
            acc[2][0] += a0.z * b.x; acc[2][1] += a0.z * b.y; acc[2][2] += a0.z * b.z; acc[2][3] += a0.z * b.w;
            acc[3][0] += a0.w * b.x; acc[3][1] += a0.w * b.y; acc[3][2] += a0.w * b.z; acc[3][3] += a0.w * b.w;
            acc[4][0] += a1.x * b.x; acc[4][1] += a1.x * b.y; acc[4][2] += a1.x * b.z; acc[4][3] += a1.x * b.w;
            acc[5][0] += a1.y * b.x; acc[5][1] += a1.y * b.y; acc[5][2] += a1.y * b.z; acc[5][3] += a1.y * b.w;
            acc[6][0] += a1.z * b.x; acc[6][1] += a1.z * b.y; acc[6][2] += a1.z * b.z; acc[6][3] += a1.z * b.w;
            acc[7][0] += a1.w * b.x; acc[7][1] += a1.w * b.y; acc[7][2] += a1.w * b.z; acc[7][3] += a1.w * b.w;
        }
        __syncthreads();
    }

    const int c = tx * 4;
#pragma unroll
    for (int i = 0; i < 8; i++) {
        const int rr = row0 + ty * 8 + i;
        if (rr < N_NODES && c < M) {
            const float s = SNS ? g_ns[rr] : 1.0f;
            union { uint2 u; __half2 h[2]; } p;
            p.h[0] = __floats2half2_rn(acc[i][0] * s, acc[i][1] * s);
            p.h[1] = __floats2half2_rn(acc[i][2] * s, acc[i][3] * s);
            *(uint2*)&Y[(size_t)rr * M + c] = p.u;
        }
    }
}

// ---------------- CSR gather (fp16 features, fp32 accum): 16 thr/node ----------------
__device__ __forceinline__ void h4_acc(float4& acc, uint2 raw, float n) {
    union { uint2 u; __half2 h[2]; } p; p.u = raw;
    const float2 a = __half22float2(p.h[0]);
    const float2 b = __half22float2(p.h[1]);
    acc.x = fmaf(a.x, n, acc.x); acc.y = fmaf(a.y, n, acc.y);
    acc.z = fmaf(b.x, n, acc.z); acc.w = fmaf(b.y, n, acc.w);
}

template <bool ESCALE>
__global__ __launch_bounds__(256) void k_gather64(const __half* __restrict__ xw,
                                                  float* __restrict__ agg) {
    const int node = blockIdx.x * 16 + (threadIdx.x >> 4);
    if (node >= N_NODES) return;
    const int f   = (threadIdx.x & 15) << 2;
    int       i   = g_rowoff[node];
    const int end = g_rowoff[node + 1];
    float4 acc = make_float4(0.f, 0.f, 0.f, 0.f);
    for (; i + 3 < end; i += 4) {
        const int s0 = __ldg(&g_csrc[i + 0]);
        const int s1 = __ldg(&g_csrc[i + 1]);
        const int s2 = __ldg(&g_csrc[i + 2]);
        const int s3 = __ldg(&g_csrc[i + 3]);
        float n0 = 1.f, n1 = 1.f, n2 = 1.f, n3 = 1.f;
        if (ESCALE) {
            n0 = __ldg(&g_ns[s0]); n1 = __ldg(&g_ns[s1]);
            n2 = __ldg(&g_ns[s2]); n3 = __ldg(&g_ns[s3]);
        }
        const uint2 r0 = __ldg((const uint2*)&xw[(size_t)s0 * 64 + f]);
        const uint2 r1 = __ldg((const uint2*)&xw[(size_t)s1 * 64 + f]);
        const uint2 r2 = __ldg((const uint2*)&xw[(size_t)s2 * 64 + f]);
        const uint2 r3 = __ldg((const uint2*)&xw[(size_t)s3 * 64 + f]);
        h4_acc(acc, r0, n0); h4_acc(acc, r1, n1);
        h4_acc(acc, r2, n2); h4_acc(acc, r3, n3);
    }
    for (; i < end; i++) {
        const int s = __ldg(&g_csrc[i]);
        const float n = ESCALE ? __ldg(&g_ns[s]) : 1.0f;
        h4_acc(acc, __ldg((const uint2*)&xw[(size_t)s * 64 + f]), n);
    }
    *(float4*)&agg[(size_t)node * 64 + f] = acc;
}

// 40-wide fp16 gather with fused final epilogue
__global__ __launch_bounds__(256) void k_gather40(const __half* __restrict__ xw,
                                                  float* __restrict__ out,
                                                  const float* __restrict__ b2) {
    const int node = blockIdx.x * 16 + (threadIdx.x >> 4);
    if (node >= N_NODES) return;
    const int f = (threadIdx.x & 15) << 2;
    if (f >= F_OUT) return;
    int       i   = g_rowoff[node];
    const int end = g_rowoff[node + 1];
    float4 acc = make_float4(0.f, 0.f, 0.f, 0.f);
    for (; i + 3 < end; i += 4) {
        const int s0 = __ldg(&g_csrc[i + 0]);
        const int s1 = __ldg(&g_csrc[i + 1]);
        const int s2 = __ldg(&g_csrc[i + 2]);
        const int s3 = __ldg(&g_csrc[i + 3]);
        h4_acc(acc, __ldg((const uint2*)&xw[(size_t)s0 * F_OUT + f]), 1.f);
        h4_acc(acc, __ldg((const uint2*)&xw[(size_t)s1 * F_OUT + f]), 1.f);
        h4_acc(acc, __ldg((const uint2*)&xw[(size_t)s2 * F_OUT + f]), 1.f);
        h4_acc(acc, __ldg((const uint2*)&xw[(size_t)s3 * F_OUT + f]), 1.f);
    }
    for (; i < end; i++) {
        const int s = __ldg(&g_csrc[i]);
        h4_acc(acc, __ldg((const uint2*)&xw[(size_t)s * F_OUT + f]), 1.f);
    }
    const float nd = g_nd[node];
    float4 o;
    o.x = fmaf(acc.x, nd, __ldg(&b2[f + 0]));
    o.y = fmaf(acc.y, nd, __ldg(&b2[f + 1]));
    o.z = fmaf(acc.z, nd, __ldg(&b2[f + 2]));
    o.w = fmaf(acc.w, nd, __ldg(&b2[f + 3]));
    *(float4*)&out[(size_t)node * F_OUT + f] = o;
}

// ---------------- host launch ----------------
extern "C" void kernel_launch(void* const* d_in, const int* in_sizes, int n_in,
                              void* d_out, int out_size) {
    (void)in_sizes; (void)n_in; (void)out_size;
    const float* h   = (const float*)d_in[0];
    const float* W0  = (const float*)d_in[1];
    const float* b0  = (const float*)d_in[2];
    const float* W1  = (const float*)d_in[3];
    const float* b1  = (const float*)d_in[4];
    const float* W2  = (const float*)d_in[5];
    const float* b2  = (const float*)d_in[6];
    const int*   src = (const int*)d_in[7];
    const int*   dst = (const int*)d_in[8];
    float* out = (float*)d_out;

    __half *pXW64, *pXW40;
    float  *pAgg;
    cudaGetSymbolAddress((void**)&pXW64, g_xw64);
    cudaGetSymbolAddress((void**)&pXW40, g_xw40);
    cudaGetSymbolAddress((void**)&pAgg,  g_agg);

    static cudaStream_t s2 = []() {
        cudaStream_t s; cudaStreamCreateWithFlags(&s, cudaStreamNonBlocking); return s;
    }();
    static cudaEvent_t evFork = []() {
        cudaEvent_t e; cudaEventCreateWithFlags(&e, cudaEventDisableTiming); return e;
    }();
    static cudaEvent_t evJoin = []() {
        cudaEvent_t e; cudaEventCreateWithFlags(&e, cudaEventDisableTiming); return e;
    }();

    const int nodeBlocks  = (N_NODES + 255) / 256;
    const int edge4Blocks = (N_EDGES / 4 + 255) / 256;
    const int gemmBlocks  = (N_NODES + 127) / 128;
    const int gathBlocks  = (N_NODES + 15) / 16;

    // ---- main: zero degrees, then fork ----
    k_zero_deg<<<(N_NODES / 4 + 255) / 256, 256>>>();
    cudaEventRecord(evFork, 0);

    // ---- side stream: GEMM0 + src-degree histogram + ns ----
    cudaStreamWaitEvent(s2, evFork, 0);
    k_gemm<F_IN, F_HID, false, false><<<gemmBlocks, 256, 0, s2>>>(h, W0, pXW64, b0);
    k_deg_src<<<edge4Blocks, 256, 0, s2>>>(src);
    k_ns<<<nodeBlocks, 256, 0, s2>>>();
    cudaEventRecord(evJoin, s2);

    // ---- main: dst histogram + CSR ----
    k_deg_dst<<<edge4Blocks, 256>>>(dst);
    k_scan_block<<<SCAN_NB, SCAN_T>>>();
    k_finalize<<<SCAN_NB, SCAN_T>>>();
    k_fill<<<edge4Blocks, 256>>>(src, dst);

    // ---- join, layer-0 gather (ns applied per edge) ----
    cudaStreamWaitEvent(0, evJoin, 0);
    k_gather64<true><<<gathBlocks, 256>>>(pXW64, pAgg);

    // layer 1
    k_gemm<F_HID, F_HID, true, true><<<gemmBlocks, 256>>>(pAgg, W1, pXW64, b0);
    k_gather64<false><<<gathBlocks, 256>>>(pXW64, pAgg);

    // layer 2 (+ fused bias/norm epilogue in gather)
    k_gemm<F_HID, F_OUT, true, true><<<gemmBlocks, 256>>>(pAgg, W2, pXW40, b1);
    k_gather40<<<gathBlocks, 256>>>(pXW40, out, b2);
}

// round 7
// speedup vs baseline: 1.3951x; 1.0510x over previous
#include <cuda_runtime.h>
#include <cuda_fp16.h>
#include <cstdint>

#define N_NODES 100000
#define N_EDGES 1600000
#define F_IN    128
#define F_HID   64
#define F_OUT   40

#define SCAN_T  1024
#define SCAN_NB ((N_NODES + SCAN_T - 1) / SCAN_T)   // 98

// ---------------- scratch (static device globals; no allocation) ----------------
__device__ int    g_degs_i[N_NODES];
__device__ int    g_degd_i[N_NODES];
__device__ float  g_ns[N_NODES];
__device__ float  g_nd[N_NODES];
__device__ int    g_incl[N_NODES];
__device__ int    g_rowoff[N_NODES + 1];
__device__ int    g_cursor[N_NODES];
__device__ int    g_partial[SCAN_NB];
__device__ int    g_csrc[N_EDGES];
__device__ __half g_xw64[(size_t)N_NODES * F_HID];   // GEMM out (gather in), fp16
__device__ __half g_xw40[(size_t)N_NODES * F_OUT];
__device__ __half g_agg [(size_t)N_NODES * F_HID];   // gather out (GEMM in), fp16

// ---------------- zero both degree arrays (int4) ----------------
__global__ void k_zero_deg() {
    int i = blockIdx.x * blockDim.x + threadIdx.x;
    if (i < N_NODES / 4) {
        ((int4*)g_degs_i)[i] = make_int4(0, 0, 0, 0);
        ((int4*)g_degd_i)[i] = make_int4(0, 0, 0, 0);
    }
}

// ---------------- degree histograms (4 edges per thread) ----------------
__global__ void k_deg_dst(const int* __restrict__ dst) {
    int i = blockIdx.x * blockDim.x + threadIdx.x;
    if (i < N_EDGES / 4) {
        const int4 d = __ldg(&((const int4*)dst)[i]);
        atomicAdd(&g_degd_i[d.x], 1);
        atomicAdd(&g_degd_i[d.y], 1);
        atomicAdd(&g_degd_i[d.z], 1);
        atomicAdd(&g_degd_i[d.w], 1);
    }
}

__global__ void k_deg_src(const int* __restrict__ src) {
    int i = blockIdx.x * blockDim.x + threadIdx.x;
    if (i < N_EDGES / 4) {
        const int4 s = __ldg(&((const int4*)src)[i]);
        atomicAdd(&g_degs_i[s.x], 1);
        atomicAdd(&g_degs_i[s.y], 1);
        atomicAdd(&g_degs_i[s.z], 1);
        atomicAdd(&g_degs_i[s.w], 1);
    }
}

__global__ void k_ns() {
    int i = blockIdx.x * blockDim.x + threadIdx.x;
    if (i < N_NODES) g_ns[i] = rsqrtf(fmaxf((float)g_degs_i[i], 1.0f));
}

// ---------------- CSR build ----------------
__global__ __launch_bounds__(SCAN_T) void k_scan_block() {
    __shared__ int ws[32];
    int g = blockIdx.x * SCAN_T + threadIdx.x;
    int lane = threadIdx.x & 31, wid = threadIdx.x >> 5;
    int x = (g < N_NODES) ? g_degd_i[g] : 0;
#pragma unroll
    for (int o = 1; o < 32; o <<= 1) {
        int y = __shfl_up_sync(0xFFFFFFFFu, x, o);
        if (lane >= o) x += y;
    }
    if (lane == 31) ws[wid] = x;
    __syncthreads();
    if (wid == 0) {
        int y = ws[lane];
#pragma unroll
        for (int o = 1; o < 32; o <<= 1) {
            int z = __shfl_up_sync(0xFFFFFFFFu, y, o);
            if (lane >= o) y += z;
        }
        ws[lane] = y;
    }
    __syncthreads();
    int incl = x + (wid > 0 ? ws[wid - 1] : 0);
    if (g < N_NODES) g_incl[g] = incl;
    if (threadIdx.x == SCAN_T - 1) g_partial[blockIdx.x] = incl;
}

// finalize: per-block recompute of the partials prefix
__global__ __launch_bounds__(SCAN_T) void k_finalize() {
    __shared__ int ws[32];
    __shared__ int s_off;
    const int tid = threadIdx.x;
    const int lane = tid & 31, w = tid >> 5;

    int v = 0;
    if (tid < SCAN_NB && tid < blockIdx.x) v = g_partial[tid];
#pragma unroll
    for (int o = 16; o > 0; o >>= 1) v += __shfl_down_sync(0xFFFFFFFFu, v, o);
    if (tid < 128 && lane == 0) ws[w] = v;
    __syncthreads();
    if (tid == 0) s_off = ws[0] + ws[1] + ws[2] + ws[3];
    __syncthreads();
    const int off = s_off;

    int g = blockIdx.x * SCAN_T + tid;
    if (g < N_NODES) {
        int dd   = g_degd_i[g];
        int incl = g_incl[g] + off;
        g_rowoff[g + 1] = incl;
        g_cursor[g] = incl - dd;
        if (g == 0) g_rowoff[0] = 0;
        g_nd[g] = rsqrtf(fmaxf((float)dd, 1.0f));
    }
}

__global__ void k_fill(const int* __restrict__ src, const int* __restrict__ dst) {
    int i = blockIdx.x * blockDim.x + threadIdx.x;
    if (i < N_EDGES / 4) {
        const int4 s = __ldg(&((const int4*)src)[i]);
        const int4 d = __ldg(&((const int4*)dst)[i]);
        g_csrc[atomicAdd(&g_cursor[d.x], 1)] = s.x;
        g_csrc[atomicAdd(&g_cursor[d.y], 1)] = s.y;
        g_csrc[atomicAdd(&g_cursor[d.z], 1)] = s.z;
        g_csrc[atomicAdd(&g_cursor[d.w], 1)] = s.w;
    }
}

// ---------------- typed quad loader for GEMM X tiles ----------------
__device__ __forceinline__ float4 load_quad(const float* p) {
    return *(const float4*)p;
}
__device__ __forceinline__ float4 load_quad(const __half* p) {
    union { uint2 u; __half2 h[2]; } r;
    r.u = *(const uint2*)p;
    const float2 a = __half22float2(r.h[0]);
    const float2 b = __half22float2(r.h[1]);
    return make_float4(a.x, a.y, b.x, b.y);
}

// ---------------- tiled fp32 GEMM -> fp16 output ----------------
// 128 rows x 64 cols, 256 threads, 8x4 microtile, K-chunks of 16.
template <int K, int M, bool PRE, bool SNS, typename TX>
__global__ __launch_bounds__(256) void k_gemm(const TX* __restrict__ X,
                                              const float* __restrict__ W,
                                              __half* __restrict__ Y,
                                              const float* __restrict__ bpre) {
    __shared__ __align__(16) float Xs[16][132];
    __shared__ __align__(16) float Ws[16][64];

    const int tid  = threadIdx.x;
    const int tx   = tid & 15;
    const int ty   = tid >> 4;
    const int row0 = blockIdx.x * 128;

    const int lr   = tid >> 1;
    const int lq   = tid & 1;
    const int lrow = row0 + lr;

    float ndv = 1.0f;
    if (PRE) ndv = (lrow < N_NODES) ? g_nd[lrow] : 0.0f;

    float acc[8][4];
#pragma unroll
    for (int i = 0; i < 8; i++)
#pragma unroll
        for (int j = 0; j < 4; j++) acc[i][j] = 0.0f;

    for (int kc = 0; kc < K; kc += 16) {
#pragma unroll
        for (int q = 0; q < 2; q++) {
            const int kq = lq + q * 2;
            float4 xv = make_float4(0.f, 0.f, 0.f, 0.f);
            if (lrow < N_NODES)
                xv = load_quad(&X[(size_t)lrow * K + kc + kq * 4]);
            if (PRE) {
                xv.x = fmaxf(fmaf(xv.x, ndv, __ldg(&bpre[kc + kq * 4 + 0])), 0.f);
                xv.y = fmaxf(fmaf(xv.y, ndv, __ldg(&bpre[kc + kq * 4 + 1])), 0.f);
                xv.z = fmaxf(fmaf(xv.z, ndv, __ldg(&bpre[kc + kq * 4 + 2])), 0.f);
                xv.w = fmaxf(fmaf(xv.w, ndv, __ldg(&bpre[kc + kq * 4 + 3])), 0.f);
            }
            Xs[kq * 4 + 0][lr] = xv.x;
            Xs[kq * 4 + 1][lr] = xv.y;
            Xs[kq * 4 + 2][lr] = xv.z;
            Xs[kq * 4 + 3][lr] = xv.w;
        }
        {
            const int wk = tid >> 4;
            const int wc = (tid & 15) * 4;
            float4 wv = make_float4(0.f, 0.f, 0.f, 0.f);
            if (wc < M)
                wv = *(const float4*)&W[(size_t)(kc + wk) * M + wc];
            *(float4*)&Ws[wk][wc] = wv;
        }
        __syncthreads();

#pragma unroll
        for (int k = 0; k < 16; k++) {
            const float4 b  = *(const float4*)&Ws[k][tx * 4];
            const float4 a0 = *(const float4*)&Xs[k][ty * 8];
            const float4 a1 = *(const float4*)&Xs[k][ty * 8 + 4];
            acc[0][0] += a0.x * b.x; acc[0][1] += a0.x * b.y; acc[0][2] += a0.x * b.z; acc[0][3] += a0.x * b.w;
            acc[1][0] += a0.y * b.x; acc[1][1] += a0.y * b.y; acc[1][2] += a0.y * b.z; acc[1][3] += a0.y * b.w;
            acc[2][0] += a0.z * b.x; acc[2][1] += a0.z * b.y; acc[2][2] += a0.z * b.z; acc[2][3] += a0.z * b.w;
            acc[3][0] += a0.w * b.x; acc[3][1] += a0.w * b.y; acc[3][2] += a0.w * b.z; acc[3][3] += a0.w * b.w;
            acc[4][0] += a1.x * b.x; acc[4][1] += a1.x * b.y; acc[4][2] += a1.x * b.z; acc[4][3] += a1.x * b.w;
            acc[5][0] += a1.y * b.x; acc[5][1] += a1.y * b.y; acc[5][2] += a1.y * b.z; acc[5][3] += a1.y * b.w;
            acc[6][0] += a1.z * b.x; acc[6][1] += a1.z * b.y; acc[6][2] += a1.z * b.z; acc[6][3] += a1.z * b.w;
            acc[7][0] += a1.w * b.x; acc[7][1] += a1.w * b.y; acc[7][2] += a1.w * b.z; acc[7][3] += a1.w * b.w;
        }
        __syncthreads();
    }

    const int c = tx * 4;
#pragma unroll
    for (int i = 0; i < 8; i++) {
        const int rr = row0 + ty * 8 + i;
        if (rr < N_NODES && c < M) {
            const float s = SNS ? g_ns[rr] : 1.0f;
            union { uint2 u; __half2 h[2]; } p;
            p.h[0] = __floats2half2_rn(acc[i][0] * s, acc[i][1] * s);
            p.h[1] = __floats2half2_rn(acc[i][2] * s, acc[i][3] * s);
            *(uint2*)&Y[(size_t)rr * M + c] = p.u;
        }
    }
}

// ---------------- CSR gather (fp16 in/out, fp32 accum): 8 thr/node, 16B loads ----------------
__device__ __forceinline__ void h8_acc(float* acc, uint4 raw, float n) {
    union { uint4 u; __half2 h[4]; } p; p.u = raw;
#pragma unroll
    for (int j = 0; j < 4; j++) {
        const float2 v = __half22float2(p.h[j]);
        acc[2 * j + 0] = fmaf(v.x, n, acc[2 * j + 0]);
        acc[2 * j + 1] = fmaf(v.y, n, acc[2 * j + 1]);
    }
}

template <bool ESCALE>
__global__ __launch_bounds__(256) void k_gather64(const __half* __restrict__ xw,
                                                  __half* __restrict__ agg) {
    const int node = blockIdx.x * 32 + (threadIdx.x >> 3);
    if (node >= N_NODES) return;
    const int f   = (threadIdx.x & 7) << 3;   // 0..56, 8 features per thread
    int       i   = g_rowoff[node];
    const int end = g_rowoff[node + 1];
    float acc[8] = {0.f, 0.f, 0.f, 0.f, 0.f, 0.f, 0.f, 0.f};

    for (; i + 3 < end; i += 4) {
        const int s0 = __ldg(&g_csrc[i + 0]);
        const int s1 = __ldg(&g_csrc[i + 1]);
        const int s2 = __ldg(&g_csrc[i + 2]);
        const int s3 = __ldg(&g_csrc[i + 3]);
        float n0 = 1.f, n1 = 1.f, n2 = 1.f, n3 = 1.f;
        if (ESCALE) {
            n0 = __ldg(&g_ns[s0]); n1 = __ldg(&g_ns[s1]);
            n2 = __ldg(&g_ns[s2]); n3 = __ldg(&g_ns[s3]);
        }
        const uint4 r0 = __ldg((const uint4*)&xw[(size_t)s0 * 64 + f]);
        const uint4 r1 = __ldg((const uint4*)&xw[(size_t)s1 * 64 + f]);
        const uint4 r2 = __ldg((const uint4*)&xw[(size_t)s2 * 64 + f]);
        const uint4 r3 = __ldg((const uint4*)&xw[(size_t)s3 * 64 + f]);
        h8_acc(acc, r0, n0); h8_acc(acc, r1, n1);
        h8_acc(acc, r2, n2); h8_acc(acc, r3, n3);
    }
    for (; i < end; i++) {
        const int s = __ldg(&g_csrc[i]);
        const float n = ESCALE ? __ldg(&g_ns[s]) : 1.0f;
        h8_acc(acc, __ldg((const uint4*)&xw[(size_t)s * 64 + f]), n);
    }

    union { uint4 u; __half2 h[4]; } o;
    o.h[0] = __floats2half2_rn(acc[0], acc[1]);
    o.h[1] = __floats2half2_rn(acc[2], acc[3]);
    o.h[2] = __floats2half2_rn(acc[4], acc[5]);
    o.h[3] = __floats2half2_rn(acc[6], acc[7]);
    *(uint4*)&agg[(size_t)node * 64 + f] = o.u;
}

// 40-wide fp16 gather with fused final epilogue (fp32 output)
__device__ __forceinline__ void h4_acc(float4& acc, uint2 raw) {
    union { uint2 u; __half2 h[2]; } p; p.u = raw;
    const float2 a = __half22float2(p.h[0]);
    const float2 b = __half22float2(p.h[1]);
    acc.x += a.x; acc.y += a.y; acc.z += b.x; acc.w += b.y;
}

__global__ __launch_bounds__(256) void k_gather40(const __half* __restrict__ xw,
                                                  float* __restrict__ out,
                                                  const float* __restrict__ b2) {
    const int node = blockIdx.x * 16 + (threadIdx.x >> 4);
    if (node >= N_NODES) return;
    const int f = (threadIdx.x & 15) << 2;
    if (f >= F_OUT) return;
    int       i   = g_rowoff[node];
    const int end = g_rowoff[node + 1];
    float4 acc = make_float4(0.f, 0.f, 0.f, 0.f);
    for (; i + 3 < end; i += 4) {
        const int s0 = __ldg(&g_csrc[i + 0]);
        const int s1 = __ldg(&g_csrc[i + 1]);
        const int s2 = __ldg(&g_csrc[i + 2]);
        const int s3 = __ldg(&g_csrc[i + 3]);
        h4_acc(acc, __ldg((const uint2*)&xw[(size_t)s0 * F_OUT + f]));
        h4_acc(acc, __ldg((const uint2*)&xw[(size_t)s1 * F_OUT + f]));
        h4_acc(acc, __ldg((const uint2*)&xw[(size_t)s2 * F_OUT + f]));
        h4_acc(acc, __ldg((const uint2*)&xw[(size_t)s3 * F_OUT + f]));
    }
    for (; i < end; i++) {
        const int s = __ldg(&g_csrc[i]);
        h4_acc(acc, __ldg((const uint2*)&xw[(size_t)s * F_OUT + f]));
    }
    const float nd = g_nd[node];
    float4 o;
    o.x = fmaf(acc.x, nd, __ldg(&b2[f + 0]));
    o.y = fmaf(acc.y, nd, __ldg(&b2[f + 1]));
    o.z = fmaf(acc.z, nd, __ldg(&b2[f + 2]));
    o.w = fmaf(acc.w, nd, __ldg(&b2[f + 3]));
    *(float4*)&out[(size_t)node * F_OUT + f] = o;
}

// ---------------- host launch ----------------
extern "C" void kernel_launch(void* const* d_in, const int* in_sizes, int n_in,
                              void* d_out, int out_size) {
    (void)in_sizes; (void)n_in; (void)out_size;
    const float* h   = (const float*)d_in[0];
    const float* W0  = (const float*)d_in[1];
    const float* b0  = (const float*)d_in[2];
    const float* W1  = (const float*)d_in[3];
    const float* b1  = (const float*)d_in[4];
    const float* W2  = (const float*)d_in[5];
    const float* b2  = (const float*)d_in[6];
    const int*   src = (const int*)d_in[7];
    const int*   dst = (const int*)d_in[8];
    float* out = (float*)d_out;

    __half *pXW64, *pXW40, *pAgg;
    cudaGetSymbolAddress((void**)&pXW64, g_xw64);
    cudaGetSymbolAddress((void**)&pXW40, g_xw40);
    cudaGetSymbolAddress((void**)&pAgg,  g_agg);

    static cudaStream_t s2 = []() {
        cudaStream_t s; cudaStreamCreateWithFlags(&s, cudaStreamNonBlocking); return s;
    }();
    static cudaEvent_t evFork = []() {
        cudaEvent_t e; cudaEventCreateWithFlags(&e, cudaEventDisableTiming); return e;
    }();
    static cudaEvent_t evJoin = []() {
        cudaEvent_t e; cudaEventCreateWithFlags(&e, cudaEventDisableTiming); return e;
    }();

    const int nodeBlocks  = (N_NODES + 255) / 256;
    const int edge4Blocks = (N_EDGES / 4 + 255) / 256;
    const int gemmBlocks  = (N_NODES + 127) / 128;
    const int gath64Blocks = (N_NODES + 31) / 32;
    const int gath40Blocks = (N_NODES + 15) / 16;

    // ---- main: zero degrees, then fork ----
    k_zero_deg<<<(N_NODES / 4 + 255) / 256, 256>>>();
    cudaEventRecord(evFork, 0);

    // ---- side stream: GEMM0 + src-degree histogram + ns ----
    cudaStreamWaitEvent(s2, evFork, 0);
    k_gemm<F_IN, F_HID, false, false><<<gemmBlocks, 256, 0, s2>>>(h, W0, pXW64, b0);
    k_deg_src<<<edge4Blocks, 256, 0, s2>>>(src);
    k_ns<<<nodeBlocks, 256, 0, s2>>>();
    cudaEventRecord(evJoin, s2);

    // ---- main: dst histogram + CSR ----
    k_deg_dst<<<edge4Blocks, 256>>>(dst);
    k_scan_block<<<SCAN_NB, SCAN_T>>>();
    k_finalize<<<SCAN_NB, SCAN_T>>>();
    k_fill<<<edge4Blocks, 256>>>(src, dst);

    // ---- join, layer-0 gather (ns applied per edge) ----
    cudaStreamWaitEvent(0, evJoin, 0);
    k_gather64<true><<<gath64Blocks, 256>>>(pXW64, pAgg);

    // layer 1
    k_gemm<F_HID, F_HID, true, true><<<gemmBlocks, 256>>>(pAgg, W1, pXW64, b0);
    k_gather64<false><<<gath64Blocks, 256>>>(pXW64, pAgg);

    // layer 2 (+ fused bias/norm epilogue in gather)
    k_gemm<F_HID, F_OUT, true, true><<<gemmBlocks, 256>>>(pAgg, W2, pXW40, b1);
    k_gather40<<<gath40Blocks, 256>>>(pXW40, out, b2);
}